// round 7
// baseline (speedup 1.0000x reference)
#include <cuda_runtime.h>
#include <cuda_fp16.h>
#include <cstdint>

#define BB 2
#define NN 256
#define EE 512
#define HH 150
#define HP 160

// smem byte offsets
#define STG_BYTES 23040  // per stage: A [128 x 80B] = 10240, B [160 x 80B] = 12800
#define SM_STG 0         // 4 stages = 92160
#define SM_W2  0         // phase2: W2T resident [160 x 336B] = 53760 (reuses stages)
#define SM_H   92160     // h: [128 x 336B] = 43008 (end 135168)
#define SM_GIH 135168    // g_i fp16 [512] = 1024
#define SM_HI  136192    // hi fp32 [160]
#define SM_B2  136832    // b2 fp32 [160]
#define SM_W3  137472    // W3 fp32 [160]
#define SM_PRB 138112    // 4 x 128 fp32 (end 140160)
#define SMEM_BYTES 140160

// device scratch
__device__ __half d_gh[BB * NN * EE];     // fp16 g
__device__ __half d_W1cTh[HP * EE];       // W1c^T [n][k] fp16, zero-padded
__device__ __half d_W2Th[HP * HP];        // W2^T  [n][k] fp16, zero-padded
__device__ float  d_hi[BB * NN * HP];     // g@W1a + b1 (fp32)
__device__ float  d_hj[BB * NN * HP];     // g@W1b (fp32 accum)
__device__ __half d_hjh[BB * NN * HP];    // fp16 copy of d_hj

// ---- helpers ----
__device__ __forceinline__ uint32_t h2mul(uint32_t a, uint32_t b) {
    uint32_t r;
    asm("mul.rn.f16x2 %0, %1, %2;" : "=r"(r) : "r"(a), "r"(b));
    return r;
}
__device__ __forceinline__ float2 h2f2(uint32_t h) {
    __half2 v = *reinterpret_cast<__half2*>(&h);
    return __half22float2(v);
}
__device__ __forceinline__ uint32_t f2h2(float lo, float hi) {
    uint32_t r;
    asm("cvt.rn.f16x2.f32 %0, %1, %2;" : "=r"(r) : "f"(hi), "f"(lo));
    return r;
}
__device__ __forceinline__ void cp16s(uint32_t dst, const void* src) {
    asm volatile("cp.async.cg.shared.global [%0], [%1], 16;" :: "r"(dst), "l"(src));
}
__device__ __forceinline__ void sts32(uint32_t a, uint32_t v) {
    asm volatile("st.shared.b32 [%0], %1;" :: "r"(a), "r"(v));
}
__device__ __forceinline__ uint32_t lds32(uint32_t a) {
    uint32_t v;
    asm volatile("ld.shared.b32 %0, [%1];" : "=r"(v) : "r"(a));
    return v;
}

#define LDSM4(r0, r1, r2, r3, a)                                              \
    asm volatile("ldmatrix.sync.aligned.m8n8.x4.shared.b16 {%0,%1,%2,%3}, [%4];" \
                 : "=r"(r0), "=r"(r1), "=r"(r2), "=r"(r3) : "r"(a))
#define LDSM2(r0, r1, a)                                                      \
    asm volatile("ldmatrix.sync.aligned.m8n8.x2.shared.b16 {%0,%1}, [%2];"    \
                 : "=r"(r0), "=r"(r1) : "r"(a))

__device__ __forceinline__ void mma16(float* d, const uint32_t* a, const uint32_t* b) {
    asm volatile(
        "mma.sync.aligned.m16n8k16.row.col.f32.f16.f16.f32 "
        "{%0,%1,%2,%3},{%4,%5,%6,%7},{%8,%9},{%0,%1,%2,%3};"
        : "+f"(d[0]), "+f"(d[1]), "+f"(d[2]), "+f"(d[3])
        : "r"(a[0]), "r"(a[1]), "r"(a[2]), "r"(a[3]), "r"(b[0]), "r"(b[1]));
}

// ---------------------------------------------------------------------------
// prep: fp16 conversions/transposes/padding + hi/hj accumulator init
// ---------------------------------------------------------------------------
__global__ void prep_kernel(const float* __restrict__ g, const float* __restrict__ W1,
                            const float* __restrict__ W2, const float* __restrict__ b1) {
    const int S0 = BB * NN * EE, S1 = HP * EE, S2 = HP * HP, S4 = BB * NN * HP;
    const int total = S0 + S1 + S2 + S4 + S4;
    for (int idx = blockIdx.x * blockDim.x + threadIdx.x; idx < total;
         idx += gridDim.x * blockDim.x) {
        int t = idx;
        if (t < S0) { d_gh[t] = __float2half(g[t]); continue; }
        t -= S0;
        if (t < S1) {
            int n = t >> 9, k = t & 511;
            d_W1cTh[t] = (n < HH) ? __float2half(W1[(size_t)(2 * EE + k) * HH + n])
                                  : __float2half(0.f);
            continue;
        }
        t -= S1;
        if (t < S2) {
            int n = t / HP, k = t % HP;
            d_W2Th[t] = (n < HH && k < HH) ? __float2half(W2[(size_t)k * HH + n])
                                           : __float2half(0.f);
            continue;
        }
        t -= S2;
        if (t < S4) { int c = t % HP; d_hi[t] = (c < HH) ? b1[c] : 0.f; continue; }
        t -= S4;
        d_hj[t] = 0.f;
    }
}

// ---------------------------------------------------------------------------
// hi/hj precompute: g@W1a (+b1 already in d_hi), g@W1b. K-split x4 + atomicAdd.
// ---------------------------------------------------------------------------
__global__ void hihj_kernel(const float* __restrict__ g, const float* __restrict__ W1) {
    __shared__ float gs[32][33];
    __shared__ float Ws[32][HP];
    const int tid = threadIdx.x;
    const int kz = blockIdx.x, rb = blockIdx.y, half = blockIdx.z;
    const int row0 = rb * 32;
    const int k0 = kz * 128;
    const int ty = tid >> 4, tx = tid & 15;

    float acc[2][10];
#pragma unroll
    for (int u = 0; u < 2; u++)
#pragma unroll
        for (int v = 0; v < 10; v++) acc[u][v] = 0.f;

    for (int kk = 0; kk < 4; kk++) {
        const int kbase = k0 + kk * 32;
        for (int q = tid; q < 32 * 32; q += 256) {
            int r = q >> 5, c = q & 31;
            gs[r][c] = g[(size_t)(row0 + r) * EE + kbase + c];
        }
        for (int q = tid; q < 32 * HP; q += 256) {
            int r = q / HP, c = q % HP;
            Ws[r][c] = (c < HH) ? W1[(size_t)(half * 512 + kbase + r) * HH + c] : 0.f;
        }
        __syncthreads();
#pragma unroll 4
        for (int k = 0; k < 32; k++) {
            float g0 = gs[ty * 2][k], g1 = gs[ty * 2 + 1][k];
#pragma unroll
            for (int v = 0; v < 10; v++) {
                float w = Ws[k][tx * 10 + v];
                acc[0][v] += g0 * w;
                acc[1][v] += g1 * w;
            }
        }
        __syncthreads();
    }
    float* dst = half ? d_hj : d_hi;
#pragma unroll
    for (int u = 0; u < 2; u++)
#pragma unroll
        for (int v = 0; v < 10; v++)
            atomicAdd(&dst[(size_t)(row0 + ty * 2 + u) * HP + tx * 10 + v], acc[u][v]);
}

__global__ void cvt_hj_kernel() {
    int t = blockIdx.x * 256 + threadIdx.x;
    if (t < BB * NN * HP) d_hjh[t] = __float2half(d_hj[t]);
}

// ---------------------------------------------------------------------------
// main fused fp16 mma kernel: CTA = (jb, i, b). 512 threads, 16 warps 4(M)x4(N).
// A-fragment scaling by g_i; B = raw W1cT streamed via 4-stage cp.async.
// ---------------------------------------------------------------------------
__global__ __launch_bounds__(512, 1) void pair_fp16(
    const float* __restrict__ ment, const float* __restrict__ b2,
    const float* __restrict__ W3, const float* __restrict__ b3,
    float* __restrict__ out) {
    extern __shared__ __align__(16) unsigned char smem[];
    const uint32_t sb = (uint32_t)__cvta_generic_to_shared(smem);
    float* hi_s = (float*)(smem + SM_HI);
    float* b2_s = (float*)(smem + SM_B2);
    float* w3_s = (float*)(smem + SM_W3);
    float* prb  = (float*)(smem + SM_PRB);

    const int tid = threadIdx.x, wid = tid >> 5, lane = tid & 31;
    const int jb = blockIdx.x, i = blockIdx.y, b = blockIdx.z;
    const int j0 = jb * 128;
    const int wm = wid >> 2, wn = wid & 3, grp = lane >> 2, tig = lane & 3;

    for (int q = tid; q < HP; q += 512) {
        hi_s[q] = d_hi[(size_t)(b * NN + i) * HP + q];
        b2_s[q] = (q < HH) ? b2[q] : 0.f;
        w3_s[q] = (q < HH) ? W3[q] : 0.f;
    }

    const __half* gj = d_gh + (size_t)(b * NN + j0) * EE;
    const __half* gi = d_gh + (size_t)(b * NN + i) * EE;

    // ldmatrix lane-address offsets (conflict-free: strides 80B / 336B)
    const uint32_t arow = (uint32_t)(wm * 32 + (lane & 7) + ((lane >> 3) & 1) * 8);
    const uint32_t aoff  = arow * 80 + (lane >> 4) * 16;
    const uint32_t aoffH = arow * 336 + (lane >> 4) * 16;
    const uint32_t b4row = (uint32_t)(wn * 40 + (lane & 7) + ((lane >> 4) & 1) * 8);
    const uint32_t b2row = (uint32_t)(wn * 40 + 32 + (lane & 7));
    const uint32_t boff4  = b4row * 80 + ((lane >> 3) & 1) * 16;
    const uint32_t boff2  = b2row * 80 + ((lane >> 3) & 1) * 16;
    const uint32_t boff4W = b4row * 336 + ((lane >> 3) & 1) * 16;
    const uint32_t boff2W = b2row * 336 + ((lane >> 3) & 1) * 16;

    // ---- prologue: gi (fp16) + stages 0..2, one commit group per stage ----
    if (tid < 64) cp16s(sb + SM_GIH + tid * 16, gi + tid * 8);
#pragma unroll
    for (int s = 0; s < 3; s++) {
        {
            int row = tid >> 2, u = tid & 3;
            cp16s(sb + SM_STG + s * STG_BYTES + row * 80 + u * 16,
                  gj + (size_t)row * EE + s * 32 + u * 8);
        }
#pragma unroll
        for (int t = 0; t < 2; t++) {
            int q = tid + t * 512;
            if (q < 640) {
                int n = q >> 2, u = q & 3;
                cp16s(sb + SM_STG + s * STG_BYTES + 10240 + n * 80 + u * 16,
                      d_W1cTh + (size_t)n * EE + s * 32 + u * 8);
            }
        }
        asm volatile("cp.async.commit_group;");
    }

    // ---- GEMM1: K=512 in 16 chunks of 32, 4-stage pipeline ----
    float acc[2][5][4];
#pragma unroll
    for (int x = 0; x < 2; x++)
#pragma unroll
        for (int y = 0; y < 5; y++)
#pragma unroll
            for (int e = 0; e < 4; e++) acc[x][y][e] = 0.f;

    for (int kc = 0; kc < 16; kc++) {
        asm volatile("cp.async.wait_group 2;");
        __syncthreads();
        if (kc < 13) {
            const int s = (kc + 3) & 3, kn = kc + 3;
            {
                int row = tid >> 2, u = tid & 3;
                cp16s(sb + SM_STG + s * STG_BYTES + row * 80 + u * 16,
                      gj + (size_t)row * EE + kn * 32 + u * 8);
            }
#pragma unroll
            for (int t = 0; t < 2; t++) {
                int q = tid + t * 512;
                if (q < 640) {
                    int n = q >> 2, u = q & 3;
                    cp16s(sb + SM_STG + s * STG_BYTES + 10240 + n * 80 + u * 16,
                          d_W1cTh + (size_t)n * EE + kn * 32 + u * 8);
                }
            }
        }
        asm volatile("cp.async.commit_group;");

        const uint32_t base = sb + SM_STG + (kc & 3) * STG_BYTES;
#pragma unroll
        for (int ks = 0; ks < 2; ks++) {
            const uint32_t g01 = lds32(sb + SM_GIH + kc * 64 + ks * 32 + tig * 4);
            const uint32_t g23 = lds32(sb + SM_GIH + kc * 64 + ks * 32 + tig * 4 + 16);
            uint32_t a[2][4], bf[5][2];
            const uint32_t abase = base + aoff + ks * 32;
            LDSM4(a[0][0], a[0][1], a[0][2], a[0][3], abase);
            LDSM4(a[1][0], a[1][1], a[1][2], a[1][3], abase + 1280);
#pragma unroll
            for (int mt = 0; mt < 2; mt++) {
                a[mt][0] = h2mul(a[mt][0], g01);
                a[mt][1] = h2mul(a[mt][1], g01);
                a[mt][2] = h2mul(a[mt][2], g23);
                a[mt][3] = h2mul(a[mt][3], g23);
            }
            const uint32_t bbase = base + 10240 + ks * 32;
            LDSM4(bf[0][0], bf[0][1], bf[1][0], bf[1][1], bbase + boff4);
            LDSM4(bf[2][0], bf[2][1], bf[3][0], bf[3][1], bbase + boff4 + 1280);
            LDSM2(bf[4][0], bf[4][1], bbase + boff2);
#pragma unroll
            for (int mt = 0; mt < 2; mt++)
#pragma unroll
                for (int nt = 0; nt < 5; nt++) mma16(acc[mt][nt], a[mt], bf[nt]);
        }
    }
    __syncthreads();   // all stage reads done before W2 overwrites stage region

    // ---- prefetch full W2T into SM_W2 (overlaps epilogue1) ----
#pragma unroll
    for (int t = 0; t < 7; t++) {
        int q = tid + t * 512;
        if (q < 3200) {
            int n = q / 20, u = q % 20;
            cp16s(sb + SM_W2 + n * 336 + u * 16, d_W2Th + (size_t)n * HP + u * 8);
        }
    }
    asm volatile("cp.async.commit_group;");

    // ---- epilogue1: h = relu(acc + hi + hj) -> fp16 in SM_H ----
#pragma unroll
    for (int mt = 0; mt < 2; mt++) {
#pragma unroll
        for (int hrow = 0; hrow < 2; hrow++) {
            const int r = wm * 32 + mt * 16 + grp + hrow * 8;
            const __half* hjrow = d_hjh + (size_t)(b * NN + j0 + r) * HP;
#pragma unroll
            for (int nt = 0; nt < 5; nt++) {
                const int col = wn * 40 + nt * 8 + 2 * tig;
                uint32_t hjp = *(const uint32_t*)(hjrow + col);
                float2 hjf = h2f2(hjp);
                float x0 = fmaxf(acc[mt][nt][hrow * 2 + 0] + hi_s[col] + hjf.x, 0.f);
                float x1 = fmaxf(acc[mt][nt][hrow * 2 + 1] + hi_s[col + 1] + hjf.y, 0.f);
                sts32(sb + SM_H + r * 336 + col * 2, f2h2(x0, x1));
            }
        }
    }
    asm volatile("cp.async.wait_group 0;");
    __syncthreads();

    // ---- GEMM2: K=160, 10 straight k16 steps. A=h(336B), B=W2T resident ----
#pragma unroll
    for (int x = 0; x < 2; x++)
#pragma unroll
        for (int y = 0; y < 5; y++)
#pragma unroll
            for (int e = 0; e < 4; e++) acc[x][y][e] = 0.f;

#pragma unroll
    for (int kk = 0; kk < 10; kk++) {
        uint32_t a[2][4], bf[5][2];
        const uint32_t abase = sb + SM_H + aoffH + kk * 32;
        LDSM4(a[0][0], a[0][1], a[0][2], a[0][3], abase);
        LDSM4(a[1][0], a[1][1], a[1][2], a[1][3], abase + 5376);
        const uint32_t bbase = sb + SM_W2 + kk * 32;
        LDSM4(bf[0][0], bf[0][1], bf[1][0], bf[1][1], bbase + boff4W);
        LDSM4(bf[2][0], bf[2][1], bf[3][0], bf[3][1], bbase + boff4W + 5376);
        LDSM2(bf[4][0], bf[4][1], bbase + boff2W);
#pragma unroll
        for (int mt = 0; mt < 2; mt++)
#pragma unroll
            for (int nt = 0; nt < 5; nt++) mma16(acc[mt][nt], a[mt], bf[nt]);
    }

    // ---- epilogue2: pair = relu(acc + b2) . W3; reduce; write out ----
#pragma unroll
    for (int mt = 0; mt < 2; mt++) {
        float s0 = 0.f, s1 = 0.f;
#pragma unroll
        for (int nt = 0; nt < 5; nt++) {
            const int col = wn * 40 + nt * 8 + 2 * tig;
            s0 += fmaxf(acc[mt][nt][0] + b2_s[col], 0.f) * w3_s[col];
            s0 += fmaxf(acc[mt][nt][1] + b2_s[col + 1], 0.f) * w3_s[col + 1];
            s1 += fmaxf(acc[mt][nt][2] + b2_s[col], 0.f) * w3_s[col];
            s1 += fmaxf(acc[mt][nt][3] + b2_s[col + 1], 0.f) * w3_s[col + 1];
        }
        s0 += __shfl_xor_sync(0xffffffffu, s0, 1);
        s0 += __shfl_xor_sync(0xffffffffu, s0, 2);
        s1 += __shfl_xor_sync(0xffffffffu, s1, 1);
        s1 += __shfl_xor_sync(0xffffffffu, s1, 2);
        if (tig == 0) {
            prb[wn * 128 + wm * 32 + mt * 16 + grp] = s0;
            prb[wn * 128 + wm * 32 + mt * 16 + grp + 8] = s1;
        }
    }
    __syncthreads();

    if (tid < 128) {
        const int j = j0 + tid;
        float pair = prb[tid] + prb[128 + tid] + prb[256 + tid] + prb[384 + tid] + b3[0];
        float mi = ment[b * NN + i];
        float mj = ment[b * NN + j];
        out[(size_t)(b * NN + i) * NN + j] = (mi + mj + pair) * (1.f / 3.f);
    }
}

// ---------------------------------------------------------------------------
extern "C" void kernel_launch(void* const* d_in, const int* in_sizes, int n_in,
                              void* d_out, int out_size) {
    const float* g  = (const float*)d_in[0];
    const float* m  = (const float*)d_in[1];
    const float* W1 = (const float*)d_in[2];
    const float* b1 = (const float*)d_in[3];
    const float* W2 = (const float*)d_in[4];
    const float* b2 = (const float*)d_in[5];
    const float* W3 = (const float*)d_in[6];
    const float* b3 = (const float*)d_in[7];
    float* out = (float*)d_out;
    (void)in_sizes; (void)n_in; (void)out_size;

    prep_kernel<<<544, 256>>>(g, W1, W2, b1);
    hihj_kernel<<<dim3(4, 16, 2), 256>>>(g, W1);
    cvt_hj_kernel<<<320, 256>>>();

    cudaFuncSetAttribute(pair_fp16, cudaFuncAttributeMaxDynamicSharedMemorySize, SMEM_BYTES);
    pair_fp16<<<dim3(NN / 128, NN, BB), 512, SMEM_BYTES>>>(m, b2, W3, b3, out);
}

// round 8
// speedup vs baseline: 1.5448x; 1.5448x over previous
#include <cuda_runtime.h>
#include <cuda_fp16.h>
#include <cstdint>

#define BB 2
#define NN 256
#define EE 512
#define HH 150
#define HP 160

// smem byte offsets
#define STG_BYTES 23040  // per stage: A [128 x 80B] = 10240, B [160 x 80B] = 12800
#define SM_STG 0         // 4 stages = 92160
#define SM_W2  0         // phase2: W2T resident [160 x 336B] = 53760 (reuses stages)
#define SM_H   92160     // h: [128 x 336B] = 43008 (end 135168)
#define SM_GIH 135168    // g_i fp16 [512] = 1024
#define SM_HI  136192    // hi fp32 [160]
#define SM_B2  136832    // b2 fp32 [160]
#define SM_W3  137472    // W3 fp32 [160]
#define SM_PRB 138112    // 4 x 128 fp32 (end 140160)
#define SMEM_BYTES 140160

// device scratch
__device__ __half d_gh[BB * NN * EE];     // fp16 g
__device__ __half d_W1cTh[HP * EE];       // W1c^T [n][k] fp16, zero-padded
__device__ __half d_W2Th[HP * HP];        // W2^T  [n][k] fp16, zero-padded
__device__ float  d_hi[BB * NN * HP];     // g@W1a + b1 (fp32)
__device__ float  d_hj[BB * NN * HP];     // g@W1b (fp32 accum)
__device__ __half d_hjh[BB * NN * HP];    // fp16 copy of d_hj

// ---- helpers ----
__device__ __forceinline__ uint32_t h2mul(uint32_t a, uint32_t b) {
    uint32_t r;
    asm("mul.rn.f16x2 %0, %1, %2;" : "=r"(r) : "r"(a), "r"(b));
    return r;
}
__device__ __forceinline__ float2 h2f2(uint32_t h) {
    __half2 v = *reinterpret_cast<__half2*>(&h);
    return __half22float2(v);
}
__device__ __forceinline__ uint32_t f2h2(float lo, float hi) {
    uint32_t r;
    asm("cvt.rn.f16x2.f32 %0, %1, %2;" : "=r"(r) : "f"(hi), "f"(lo));
    return r;
}
__device__ __forceinline__ void cp16s(uint32_t dst, const void* src) {
    asm volatile("cp.async.cg.shared.global [%0], [%1], 16;" :: "r"(dst), "l"(src));
}
__device__ __forceinline__ void sts32(uint32_t a, uint32_t v) {
    asm volatile("st.shared.b32 [%0], %1;" :: "r"(a), "r"(v));
}
__device__ __forceinline__ uint32_t lds32(uint32_t a) {
    uint32_t v;
    asm volatile("ld.shared.b32 %0, [%1];" : "=r"(v) : "r"(a));
    return v;
}

#define LDSM4(r0, r1, r2, r3, a)                                              \
    asm volatile("ldmatrix.sync.aligned.m8n8.x4.shared.b16 {%0,%1,%2,%3}, [%4];" \
                 : "=r"(r0), "=r"(r1), "=r"(r2), "=r"(r3) : "r"(a))
#define LDSM2(r0, r1, a)                                                      \
    asm volatile("ldmatrix.sync.aligned.m8n8.x2.shared.b16 {%0,%1}, [%2];"    \
                 : "=r"(r0), "=r"(r1) : "r"(a))

__device__ __forceinline__ void mma16(float* d, const uint32_t* a, const uint32_t* b) {
    asm volatile(
        "mma.sync.aligned.m16n8k16.row.col.f32.f16.f16.f32 "
        "{%0,%1,%2,%3},{%4,%5,%6,%7},{%8,%9},{%0,%1,%2,%3};"
        : "+f"(d[0]), "+f"(d[1]), "+f"(d[2]), "+f"(d[3])
        : "r"(a[0]), "r"(a[1]), "r"(a[2]), "r"(a[3]), "r"(b[0]), "r"(b[1]));
}

// ---------------------------------------------------------------------------
// prep: fp16 conversions/transposes/padding + hi/hj accumulator init
// ---------------------------------------------------------------------------
__global__ void prep_kernel(const float* __restrict__ g, const float* __restrict__ W1,
                            const float* __restrict__ W2, const float* __restrict__ b1) {
    const int S0 = BB * NN * EE, S1 = HP * EE, S2 = HP * HP, S4 = BB * NN * HP;
    const int total = S0 + S1 + S2 + S4 + S4;
    for (int idx = blockIdx.x * blockDim.x + threadIdx.x; idx < total;
         idx += gridDim.x * blockDim.x) {
        int t = idx;
        if (t < S0) { d_gh[t] = __float2half(g[t]); continue; }
        t -= S0;
        if (t < S1) {
            int n = t >> 9, k = t & 511;
            d_W1cTh[t] = (n < HH) ? __float2half(W1[(size_t)(2 * EE + k) * HH + n])
                                  : __float2half(0.f);
            continue;
        }
        t -= S1;
        if (t < S2) {
            int n = t / HP, k = t % HP;
            d_W2Th[t] = (n < HH && k < HH) ? __float2half(W2[(size_t)k * HH + n])
                                           : __float2half(0.f);
            continue;
        }
        t -= S2;
        if (t < S4) { int c = t % HP; d_hi[t] = (c < HH) ? b1[c] : 0.f; continue; }
        t -= S4;
        d_hj[t] = 0.f;
    }
}

// ---------------------------------------------------------------------------
// hi/hj precompute: g@W1a (+b1 already in d_hi), g@W1b. K-split x4 + atomicAdd.
// ---------------------------------------------------------------------------
__global__ void hihj_kernel(const float* __restrict__ g, const float* __restrict__ W1) {
    __shared__ float gs[32][33];
    __shared__ float Ws[32][HP];
    const int tid = threadIdx.x;
    const int kz = blockIdx.x, rb = blockIdx.y, half = blockIdx.z;
    const int row0 = rb * 32;
    const int k0 = kz * 128;
    const int ty = tid >> 4, tx = tid & 15;

    float acc[2][10];
#pragma unroll
    for (int u = 0; u < 2; u++)
#pragma unroll
        for (int v = 0; v < 10; v++) acc[u][v] = 0.f;

    for (int kk = 0; kk < 4; kk++) {
        const int kbase = k0 + kk * 32;
        for (int q = tid; q < 32 * 32; q += 256) {
            int r = q >> 5, c = q & 31;
            gs[r][c] = g[(size_t)(row0 + r) * EE + kbase + c];
        }
        for (int q = tid; q < 32 * HP; q += 256) {
            int r = q / HP, c = q % HP;
            Ws[r][c] = (c < HH) ? W1[(size_t)(half * 512 + kbase + r) * HH + c] : 0.f;
        }
        __syncthreads();
#pragma unroll 4
        for (int k = 0; k < 32; k++) {
            float g0 = gs[ty * 2][k], g1 = gs[ty * 2 + 1][k];
#pragma unroll
            for (int v = 0; v < 10; v++) {
                float w = Ws[k][tx * 10 + v];
                acc[0][v] += g0 * w;
                acc[1][v] += g1 * w;
            }
        }
        __syncthreads();
    }
    float* dst = half ? d_hj : d_hi;
#pragma unroll
    for (int u = 0; u < 2; u++)
#pragma unroll
        for (int v = 0; v < 10; v++)
            atomicAdd(&dst[(size_t)(row0 + ty * 2 + u) * HP + tx * 10 + v], acc[u][v]);
}

__global__ void cvt_hj_kernel() {
    int t = blockIdx.x * 256 + threadIdx.x;
    if (t < BB * NN * HP) d_hjh[t] = __float2half(d_hj[t]);
}

// ---------------------------------------------------------------------------
// main fused fp16 mma kernel: CTA = (jb, i, b). 512 threads, 16 warps 4(M)x4(N).
// A-fragment scaling by g_i; B = raw W1cT streamed via 4-stage cp.async.
// ---------------------------------------------------------------------------
__global__ __launch_bounds__(512, 1) void pair_fp16(
    const float* __restrict__ ment, const float* __restrict__ b2,
    const float* __restrict__ W3, const float* __restrict__ b3,
    float* __restrict__ out) {
    extern __shared__ __align__(16) unsigned char smem[];
    const uint32_t sb = (uint32_t)__cvta_generic_to_shared(smem);
    float* hi_s = (float*)(smem + SM_HI);
    float* b2_s = (float*)(smem + SM_B2);
    float* w3_s = (float*)(smem + SM_W3);
    float* prb  = (float*)(smem + SM_PRB);

    const int tid = threadIdx.x, wid = tid >> 5, lane = tid & 31;
    const int jb = blockIdx.x, i = blockIdx.y, b = blockIdx.z;
    const int j0 = jb * 128;
    const int wm = wid >> 2, wn = wid & 3, grp = lane >> 2, tig = lane & 3;

    for (int q = tid; q < HP; q += 512) {
        hi_s[q] = d_hi[(size_t)(b * NN + i) * HP + q];
        b2_s[q] = (q < HH) ? b2[q] : 0.f;
        w3_s[q] = (q < HH) ? W3[q] : 0.f;
    }

    const __half* gj = d_gh + (size_t)(b * NN + j0) * EE;
    const __half* gi = d_gh + (size_t)(b * NN + i) * EE;

    // ldmatrix lane-address offsets (conflict-free: strides 80B / 336B)
    const uint32_t arow = (uint32_t)(wm * 32 + (lane & 7) + ((lane >> 3) & 1) * 8);
    const uint32_t aoff  = arow * 80 + (lane >> 4) * 16;
    const uint32_t aoffH = arow * 336 + (lane >> 4) * 16;
    const uint32_t b4row = (uint32_t)(wn * 40 + (lane & 7) + ((lane >> 4) & 1) * 8);
    const uint32_t b2row = (uint32_t)(wn * 40 + 32 + (lane & 7));
    const uint32_t boff4  = b4row * 80 + ((lane >> 3) & 1) * 16;
    const uint32_t boff2  = b2row * 80 + ((lane >> 3) & 1) * 16;
    const uint32_t boff4W = b4row * 336 + ((lane >> 3) & 1) * 16;
    const uint32_t boff2W = b2row * 336 + ((lane >> 3) & 1) * 16;

    // ---- prologue: gi (fp16) + stages 0..2, one commit group per stage ----
    if (tid < 64) cp16s(sb + SM_GIH + tid * 16, gi + tid * 8);
#pragma unroll
    for (int s = 0; s < 3; s++) {
        {
            int row = tid >> 2, u = tid & 3;
            cp16s(sb + SM_STG + s * STG_BYTES + row * 80 + u * 16,
                  gj + (size_t)row * EE + s * 32 + u * 8);
        }
#pragma unroll
        for (int t = 0; t < 2; t++) {
            int q = tid + t * 512;
            if (q < 640) {
                int n = q >> 2, u = q & 3;
                cp16s(sb + SM_STG + s * STG_BYTES + 10240 + n * 80 + u * 16,
                      d_W1cTh + (size_t)n * EE + s * 32 + u * 8);
            }
        }
        asm volatile("cp.async.commit_group;");
    }

    // ---- GEMM1: K=512 in 16 chunks of 32, 4-stage pipeline ----
    float acc[2][5][4];
#pragma unroll
    for (int x = 0; x < 2; x++)
#pragma unroll
        for (int y = 0; y < 5; y++)
#pragma unroll
            for (int e = 0; e < 4; e++) acc[x][y][e] = 0.f;

    for (int kc = 0; kc < 16; kc++) {
        asm volatile("cp.async.wait_group 2;");
        __syncthreads();
        if (kc < 13) {
            const int s = (kc + 3) & 3, kn = kc + 3;
            {
                int row = tid >> 2, u = tid & 3;
                cp16s(sb + SM_STG + s * STG_BYTES + row * 80 + u * 16,
                      gj + (size_t)row * EE + kn * 32 + u * 8);
            }
#pragma unroll
            for (int t = 0; t < 2; t++) {
                int q = tid + t * 512;
                if (q < 640) {
                    int n = q >> 2, u = q & 3;
                    cp16s(sb + SM_STG + s * STG_BYTES + 10240 + n * 80 + u * 16,
                          d_W1cTh + (size_t)n * EE + kn * 32 + u * 8);
                }
            }
        }
        asm volatile("cp.async.commit_group;");

        const uint32_t base = sb + SM_STG + (kc & 3) * STG_BYTES;
#pragma unroll
        for (int ks = 0; ks < 2; ks++) {
            const uint32_t g01 = lds32(sb + SM_GIH + kc * 64 + ks * 32 + tig * 4);
            const uint32_t g23 = lds32(sb + SM_GIH + kc * 64 + ks * 32 + tig * 4 + 16);
            uint32_t a[2][4], bf[5][2];
            const uint32_t abase = base + aoff + ks * 32;
            LDSM4(a[0][0], a[0][1], a[0][2], a[0][3], abase);
            LDSM4(a[1][0], a[1][1], a[1][2], a[1][3], abase + 1280);
#pragma unroll
            for (int mt = 0; mt < 2; mt++) {
                a[mt][0] = h2mul(a[mt][0], g01);
                a[mt][1] = h2mul(a[mt][1], g01);
                a[mt][2] = h2mul(a[mt][2], g23);
                a[mt][3] = h2mul(a[mt][3], g23);
            }
            const uint32_t bbase = base + 10240 + ks * 32;
            LDSM4(bf[0][0], bf[0][1], bf[1][0], bf[1][1], bbase + boff4);
            LDSM4(bf[2][0], bf[2][1], bf[3][0], bf[3][1], bbase + boff4 + 1280);
            LDSM2(bf[4][0], bf[4][1], bbase + boff2);
#pragma unroll
            for (int mt = 0; mt < 2; mt++)
#pragma unroll
                for (int nt = 0; nt < 5; nt++) mma16(acc[mt][nt], a[mt], bf[nt]);
        }
    }
    __syncthreads();   // all stage reads done before W2 overwrites stage region

    // ---- prefetch full W2T into SM_W2 (overlaps epilogue1) ----
#pragma unroll
    for (int t = 0; t < 7; t++) {
        int q = tid + t * 512;
        if (q < 3200) {
            int n = q / 20, u = q % 20;
            cp16s(sb + SM_W2 + n * 336 + u * 16, d_W2Th + (size_t)n * HP + u * 8);
        }
    }
    asm volatile("cp.async.commit_group;");

    // ---- epilogue1: h = relu(acc + hi + hj) -> fp16 in SM_H ----
#pragma unroll
    for (int mt = 0; mt < 2; mt++) {
#pragma unroll
        for (int hrow = 0; hrow < 2; hrow++) {
            const int r = wm * 32 + mt * 16 + grp + hrow * 8;
            const __half* hjrow = d_hjh + (size_t)(b * NN + j0 + r) * HP;
#pragma unroll
            for (int nt = 0; nt < 5; nt++) {
                const int col = wn * 40 + nt * 8 + 2 * tig;
                uint32_t hjp = *(const uint32_t*)(hjrow + col);
                float2 hjf = h2f2(hjp);
                float x0 = fmaxf(acc[mt][nt][hrow * 2 + 0] + hi_s[col] + hjf.x, 0.f);
                float x1 = fmaxf(acc[mt][nt][hrow * 2 + 1] + hi_s[col + 1] + hjf.y, 0.f);
                sts32(sb + SM_H + r * 336 + col * 2, f2h2(x0, x1));
            }
        }
    }
    asm volatile("cp.async.wait_group 0;");
    __syncthreads();

    // ---- GEMM2: K=160, 10 straight k16 steps. A=h(336B), B=W2T resident ----
#pragma unroll
    for (int x = 0; x < 2; x++)
#pragma unroll
        for (int y = 0; y < 5; y++)
#pragma unroll
            for (int e = 0; e < 4; e++) acc[x][y][e] = 0.f;

#pragma unroll
    for (int kk = 0; kk < 10; kk++) {
        uint32_t a[2][4], bf[5][2];
        const uint32_t abase = sb + SM_H + aoffH + kk * 32;
        LDSM4(a[0][0], a[0][1], a[0][2], a[0][3], abase);
        LDSM4(a[1][0], a[1][1], a[1][2], a[1][3], abase + 5376);
        const uint32_t bbase = sb + SM_W2 + kk * 32;
        LDSM4(bf[0][0], bf[0][1], bf[1][0], bf[1][1], bbase + boff4W);
        LDSM4(bf[2][0], bf[2][1], bf[3][0], bf[3][1], bbase + boff4W + 5376);
        LDSM2(bf[4][0], bf[4][1], bbase + boff2W);
#pragma unroll
        for (int mt = 0; mt < 2; mt++)
#pragma unroll
            for (int nt = 0; nt < 5; nt++) mma16(acc[mt][nt], a[mt], bf[nt]);
    }

    // ---- epilogue2: pair = relu(acc + b2) . W3; reduce; write out ----
#pragma unroll
    for (int mt = 0; mt < 2; mt++) {
        float s0 = 0.f, s1 = 0.f;
#pragma unroll
        for (int nt = 0; nt < 5; nt++) {
            const int col = wn * 40 + nt * 8 + 2 * tig;
            s0 += fmaxf(acc[mt][nt][0] + b2_s[col], 0.f) * w3_s[col];
            s0 += fmaxf(acc[mt][nt][1] + b2_s[col + 1], 0.f) * w3_s[col + 1];
            s1 += fmaxf(acc[mt][nt][2] + b2_s[col], 0.f) * w3_s[col];
            s1 += fmaxf(acc[mt][nt][3] + b2_s[col + 1], 0.f) * w3_s[col + 1];
        }
        s0 += __shfl_xor_sync(0xffffffffu, s0, 1);
        s0 += __shfl_xor_sync(0xffffffffu, s0, 2);
        s1 += __shfl_xor_sync(0xffffffffu, s1, 1);
        s1 += __shfl_xor_sync(0xffffffffu, s1, 2);
        if (tig == 0) {
            prb[wn * 128 + wm * 32 + mt * 16 + grp] = s0;
            prb[wn * 128 + wm * 32 + mt * 16 + grp + 8] = s1;
        }
    }
    __syncthreads();

    if (tid < 128) {
        const int j = j0 + tid;
        float pair = prb[tid] + prb[128 + tid] + prb[256 + tid] + prb[384 + tid] + b3[0];
        float mi = ment[b * NN + i];
        float mj = ment[b * NN + j];
        out[(size_t)(b * NN + i) * NN + j] = (mi + mj + pair) * (1.f / 3.f);
    }
}

// ---------------------------------------------------------------------------
extern "C" void kernel_launch(void* const* d_in, const int* in_sizes, int n_in,
                              void* d_out, int out_size) {
    const float* g  = (const float*)d_in[0];
    const float* m  = (const float*)d_in[1];
    const float* W1 = (const float*)d_in[2];
    const float* b1 = (const float*)d_in[3];
    const float* W2 = (const float*)d_in[4];
    const float* b2 = (const float*)d_in[5];
    const float* W3 = (const float*)d_in[6];
    const float* b3 = (const float*)d_in[7];
    float* out = (float*)d_out;
    (void)in_sizes; (void)n_in; (void)out_size;

    prep_kernel<<<544, 256>>>(g, W1, W2, b1);
    hihj_kernel<<<dim3(4, 16, 2), 256>>>(g, W1);
    cvt_hj_kernel<<<320, 256>>>();

    cudaFuncSetAttribute(pair_fp16, cudaFuncAttributeMaxDynamicSharedMemorySize, SMEM_BYTES);
    pair_fp16<<<dim3(NN / 128, NN, BB), 512, SMEM_BYTES>>>(m, b2, W3, b3, out);
}

// round 9
// speedup vs baseline: 1.6150x; 1.0454x over previous
#include <cuda_runtime.h>
#include <cuda_fp16.h>
#include <cstdint>

#define BB 2
#define NN 256
#define EE 512
#define HH 150
#define HP 160

// smem byte offsets (per 256-thread CTA, M=64)
#define STG_BYTES 17920  // A [64 x 80B] = 5120 + B [160 x 80B] = 12800
#define SM_STG 0         // 4 stages = 71680
#define SM_W2  0         // phase2: W2T resident [160 x 336B] = 53760 (reuses stages)
#define SM_H   71680     // h: [64 x 336B] = 21504 (end 93184)
#define SM_GIH 93184     // g_i fp16 [512] = 1024
#define SM_HI  94208     // hi fp32 [160]
#define SM_B2  94848     // b2 fp32 [160]
#define SM_W3  95488     // W3 fp32 [160]
#define SM_PRB 96128     // 4 x 64 fp32 (end 97152)
#define SMEM_BYTES 97152

// device scratch
__device__ __half d_gh[BB * NN * EE];     // fp16 g
__device__ __half d_W1cTh[HP * EE];       // W1c^T [n][k] fp16, zero-padded
__device__ __half d_W2Th[HP * HP];        // W2^T  [n][k] fp16, zero-padded
__device__ float  d_hi[BB * NN * HP];     // g@W1a + b1 (fp32)
__device__ float  d_hj[BB * NN * HP];     // g@W1b (fp32 accum)
__device__ __half d_hjh[BB * NN * HP];    // fp16 copy of d_hj

// ---- helpers ----
__device__ __forceinline__ uint32_t h2mul(uint32_t a, uint32_t b) {
    uint32_t r;
    asm("mul.rn.f16x2 %0, %1, %2;" : "=r"(r) : "r"(a), "r"(b));
    return r;
}
__device__ __forceinline__ float2 h2f2(uint32_t h) {
    __half2 v = *reinterpret_cast<__half2*>(&h);
    return __half22float2(v);
}
__device__ __forceinline__ uint32_t f2h2(float lo, float hi) {
    uint32_t r;
    asm("cvt.rn.f16x2.f32 %0, %1, %2;" : "=r"(r) : "f"(hi), "f"(lo));
    return r;
}
__device__ __forceinline__ void cp16s(uint32_t dst, const void* src) {
    asm volatile("cp.async.cg.shared.global [%0], [%1], 16;" :: "r"(dst), "l"(src));
}
__device__ __forceinline__ void sts32(uint32_t a, uint32_t v) {
    asm volatile("st.shared.b32 [%0], %1;" :: "r"(a), "r"(v));
}
__device__ __forceinline__ uint32_t lds32(uint32_t a) {
    uint32_t v;
    asm volatile("ld.shared.b32 %0, [%1];" : "=r"(v) : "r"(a));
    return v;
}

#define LDSM4(r0, r1, r2, r3, a)                                              \
    asm volatile("ldmatrix.sync.aligned.m8n8.x4.shared.b16 {%0,%1,%2,%3}, [%4];" \
                 : "=r"(r0), "=r"(r1), "=r"(r2), "=r"(r3) : "r"(a))
#define LDSM2(r0, r1, a)                                                      \
    asm volatile("ldmatrix.sync.aligned.m8n8.x2.shared.b16 {%0,%1}, [%2];"    \
                 : "=r"(r0), "=r"(r1) : "r"(a))

__device__ __forceinline__ void mma16(float* d, const uint32_t* a, const uint32_t* b) {
    asm volatile(
        "mma.sync.aligned.m16n8k16.row.col.f32.f16.f16.f32 "
        "{%0,%1,%2,%3},{%4,%5,%6,%7},{%8,%9},{%0,%1,%2,%3};"
        : "+f"(d[0]), "+f"(d[1]), "+f"(d[2]), "+f"(d[3])
        : "r"(a[0]), "r"(a[1]), "r"(a[2]), "r"(a[3]), "r"(b[0]), "r"(b[1]));
}

// ---------------------------------------------------------------------------
// prep: fp16 conversions/transposes/padding + hi/hj accumulator init
// ---------------------------------------------------------------------------
__global__ void prep_kernel(const float* __restrict__ g, const float* __restrict__ W1,
                            const float* __restrict__ W2, const float* __restrict__ b1) {
    const int S0 = BB * NN * EE, S1 = HP * EE, S2 = HP * HP, S4 = BB * NN * HP;
    const int total = S0 + S1 + S2 + S4 + S4;
    for (int idx = blockIdx.x * blockDim.x + threadIdx.x; idx < total;
         idx += gridDim.x * blockDim.x) {
        int t = idx;
        if (t < S0) { d_gh[t] = __float2half(g[t]); continue; }
        t -= S0;
        if (t < S1) {
            int n = t >> 9, k = t & 511;
            d_W1cTh[t] = (n < HH) ? __float2half(W1[(size_t)(2 * EE + k) * HH + n])
                                  : __float2half(0.f);
            continue;
        }
        t -= S1;
        if (t < S2) {
            int n = t / HP, k = t % HP;
            d_W2Th[t] = (n < HH && k < HH) ? __float2half(W2[(size_t)k * HH + n])
                                           : __float2half(0.f);
            continue;
        }
        t -= S2;
        if (t < S4) { int c = t % HP; d_hi[t] = (c < HH) ? b1[c] : 0.f; continue; }
        t -= S4;
        d_hj[t] = 0.f;
    }
}

// ---------------------------------------------------------------------------
// hi/hj precompute: g@W1a (+b1 already in d_hi), g@W1b. K-split x4 + atomicAdd.
// ---------------------------------------------------------------------------
__global__ void hihj_kernel(const float* __restrict__ g, const float* __restrict__ W1) {
    __shared__ float gs[32][33];
    __shared__ float Ws[32][HP];
    const int tid = threadIdx.x;
    const int kz = blockIdx.x, rb = blockIdx.y, half = blockIdx.z;
    const int row0 = rb * 32;
    const int k0 = kz * 128;
    const int ty = tid >> 4, tx = tid & 15;

    float acc[2][10];
#pragma unroll
    for (int u = 0; u < 2; u++)
#pragma unroll
        for (int v = 0; v < 10; v++) acc[u][v] = 0.f;

    for (int kk = 0; kk < 4; kk++) {
        const int kbase = k0 + kk * 32;
        for (int q = tid; q < 32 * 32; q += 256) {
            int r = q >> 5, c = q & 31;
            gs[r][c] = g[(size_t)(row0 + r) * EE + kbase + c];
        }
        for (int q = tid; q < 32 * HP; q += 256) {
            int r = q / HP, c = q % HP;
            Ws[r][c] = (c < HH) ? W1[(size_t)(half * 512 + kbase + r) * HH + c] : 0.f;
        }
        __syncthreads();
#pragma unroll 4
        for (int k = 0; k < 32; k++) {
            float g0 = gs[ty * 2][k], g1 = gs[ty * 2 + 1][k];
#pragma unroll
            for (int v = 0; v < 10; v++) {
                float w = Ws[k][tx * 10 + v];
                acc[0][v] += g0 * w;
                acc[1][v] += g1 * w;
            }
        }
        __syncthreads();
    }
    float* dst = half ? d_hj : d_hi;
#pragma unroll
    for (int u = 0; u < 2; u++)
#pragma unroll
        for (int v = 0; v < 10; v++)
            atomicAdd(&dst[(size_t)(row0 + ty * 2 + u) * HP + tx * 10 + v], acc[u][v]);
}

__global__ void cvt_hj_kernel() {
    int t = blockIdx.x * 256 + threadIdx.x;
    if (t < BB * NN * HP) d_hjh[t] = __float2half(d_hj[t]);
}

// ---------------------------------------------------------------------------
// main fused fp16 mma kernel: CTA = (jb, i, b), M=64 j-rows, 256 threads,
// 8 warps 2(M)x4(N), warp tile 32x40. Two CTAs co-resident per SM.
// ---------------------------------------------------------------------------
__global__ __launch_bounds__(256, 2) void pair_fp16(
    const float* __restrict__ ment, const float* __restrict__ b2,
    const float* __restrict__ W3, const float* __restrict__ b3,
    float* __restrict__ out) {
    extern __shared__ __align__(16) unsigned char smem[];
    const uint32_t sb = (uint32_t)__cvta_generic_to_shared(smem);
    float* hi_s = (float*)(smem + SM_HI);
    float* b2_s = (float*)(smem + SM_B2);
    float* w3_s = (float*)(smem + SM_W3);
    float* prb  = (float*)(smem + SM_PRB);

    const int tid = threadIdx.x, wid = tid >> 5, lane = tid & 31;
    const int jb = blockIdx.x, i = blockIdx.y, b = blockIdx.z;
    const int j0 = jb * 64;
    const int wm = wid >> 2, wn = wid & 3, grp = lane >> 2, tig = lane & 3;

    for (int q = tid; q < HP; q += 256) {
        hi_s[q] = d_hi[(size_t)(b * NN + i) * HP + q];
        b2_s[q] = (q < HH) ? b2[q] : 0.f;
        w3_s[q] = (q < HH) ? W3[q] : 0.f;
    }

    const __half* gj = d_gh + (size_t)(b * NN + j0) * EE;
    const __half* gi = d_gh + (size_t)(b * NN + i) * EE;

    // ldmatrix lane-address offsets (conflict-free: strides 80B / 336B)
    const uint32_t arow = (uint32_t)(wm * 32 + (lane & 7) + ((lane >> 3) & 1) * 8);
    const uint32_t aoff  = arow * 80 + (lane >> 4) * 16;
    const uint32_t aoffH = arow * 336 + (lane >> 4) * 16;
    const uint32_t b4row = (uint32_t)(wn * 40 + (lane & 7) + ((lane >> 4) & 1) * 8);
    const uint32_t b2row = (uint32_t)(wn * 40 + 32 + (lane & 7));
    const uint32_t boff4  = b4row * 80 + ((lane >> 3) & 1) * 16;
    const uint32_t boff2  = b2row * 80 + ((lane >> 3) & 1) * 16;
    const uint32_t boff4W = b4row * 336 + ((lane >> 3) & 1) * 16;
    const uint32_t boff2W = b2row * 336 + ((lane >> 3) & 1) * 16;

    // ---- prologue: gi (fp16) + stages 0..2 ----
    if (tid < 64) cp16s(sb + SM_GIH + tid * 16, gi + tid * 8);
#pragma unroll
    for (int s = 0; s < 3; s++) {
        if (tid < 256) {  // A: 64 rows x 4 x 16B
            int row = tid >> 2, u = tid & 3;
            cp16s(sb + SM_STG + s * STG_BYTES + row * 80 + u * 16,
                  gj + (size_t)row * EE + s * 32 + u * 8);
        }
#pragma unroll
        for (int t = 0; t < 3; t++) {  // B: 160 rows x 4 x 16B = 640
            int q = tid + t * 256;
            if (q < 640) {
                int n = q >> 2, u = q & 3;
                cp16s(sb + SM_STG + s * STG_BYTES + 5120 + n * 80 + u * 16,
                      d_W1cTh + (size_t)n * EE + s * 32 + u * 8);
            }
        }
        asm volatile("cp.async.commit_group;");
    }

    // ---- GEMM1: K=512 in 16 chunks of 32, 4-stage pipeline ----
    float acc[2][5][4];
#pragma unroll
    for (int x = 0; x < 2; x++)
#pragma unroll
        for (int y = 0; y < 5; y++)
#pragma unroll
            for (int e = 0; e < 4; e++) acc[x][y][e] = 0.f;

    for (int kc = 0; kc < 16; kc++) {
        asm volatile("cp.async.wait_group 2;");
        __syncthreads();
        if (kc < 13) {
            const int s = (kc + 3) & 3, kn = kc + 3;
            {
                int row = tid >> 2, u = tid & 3;
                cp16s(sb + SM_STG + s * STG_BYTES + row * 80 + u * 16,
                      gj + (size_t)row * EE + kn * 32 + u * 8);
            }
#pragma unroll
            for (int t = 0; t < 3; t++) {
                int q = tid + t * 256;
                if (q < 640) {
                    int n = q >> 2, u = q & 3;
                    cp16s(sb + SM_STG + s * STG_BYTES + 5120 + n * 80 + u * 16,
                          d_W1cTh + (size_t)n * EE + kn * 32 + u * 8);
                }
            }
        }
        asm volatile("cp.async.commit_group;");

        const uint32_t base = sb + SM_STG + (kc & 3) * STG_BYTES;
#pragma unroll
        for (int ks = 0; ks < 2; ks++) {
            const uint32_t g01 = lds32(sb + SM_GIH + kc * 64 + ks * 32 + tig * 4);
            const uint32_t g23 = lds32(sb + SM_GIH + kc * 64 + ks * 32 + tig * 4 + 16);
            uint32_t a[2][4], bf[5][2];
            const uint32_t abase = base + aoff + ks * 32;
            LDSM4(a[0][0], a[0][1], a[0][2], a[0][3], abase);
            LDSM4(a[1][0], a[1][1], a[1][2], a[1][3], abase + 1280);
#pragma unroll
            for (int mt = 0; mt < 2; mt++) {
                a[mt][0] = h2mul(a[mt][0], g01);
                a[mt][1] = h2mul(a[mt][1], g01);
                a[mt][2] = h2mul(a[mt][2], g23);
                a[mt][3] = h2mul(a[mt][3], g23);
            }
            const uint32_t bbase = base + 5120 + ks * 32;
            LDSM4(bf[0][0], bf[0][1], bf[1][0], bf[1][1], bbase + boff4);
            LDSM4(bf[2][0], bf[2][1], bf[3][0], bf[3][1], bbase + boff4 + 1280);
            LDSM2(bf[4][0], bf[4][1], bbase + boff2);
#pragma unroll
            for (int mt = 0; mt < 2; mt++)
#pragma unroll
                for (int nt = 0; nt < 5; nt++) mma16(acc[mt][nt], a[mt], bf[nt]);
        }
    }
    __syncthreads();   // all stage reads done before W2 overwrites stage region

    // ---- prefetch full W2T into SM_W2 (overlaps epilogue1) ----
#pragma unroll
    for (int t = 0; t < 13; t++) {
        int q = tid + t * 256;
        if (q < 3200) {
            int n = q / 20, u = q % 20;
            cp16s(sb + SM_W2 + n * 336 + u * 16, d_W2Th + (size_t)n * HP + u * 8);
        }
    }
    asm volatile("cp.async.commit_group;");

    // ---- epilogue1: h = relu(acc + hi + hj) -> fp16 in SM_H ----
#pragma unroll
    for (int mt = 0; mt < 2; mt++) {
#pragma unroll
        for (int hrow = 0; hrow < 2; hrow++) {
            const int r = wm * 32 + mt * 16 + grp + hrow * 8;
            const __half* hjrow = d_hjh + (size_t)(b * NN + j0 + r) * HP;
#pragma unroll
            for (int nt = 0; nt < 5; nt++) {
                const int col = wn * 40 + nt * 8 + 2 * tig;
                uint32_t hjp = *(const uint32_t*)(hjrow + col);
                float2 hjf = h2f2(hjp);
                float x0 = fmaxf(acc[mt][nt][hrow * 2 + 0] + hi_s[col] + hjf.x, 0.f);
                float x1 = fmaxf(acc[mt][nt][hrow * 2 + 1] + hi_s[col + 1] + hjf.y, 0.f);
                sts32(sb + SM_H + r * 336 + col * 2, f2h2(x0, x1));
            }
        }
    }
    asm volatile("cp.async.wait_group 0;");
    __syncthreads();

    // ---- GEMM2: K=160, 10 straight k16 steps. A=h(336B), B=W2T resident ----
#pragma unroll
    for (int x = 0; x < 2; x++)
#pragma unroll
        for (int y = 0; y < 5; y++)
#pragma unroll
            for (int e = 0; e < 4; e++) acc[x][y][e] = 0.f;

#pragma unroll
    for (int kk = 0; kk < 10; kk++) {
        uint32_t a[2][4], bf[5][2];
        const uint32_t abase = sb + SM_H + aoffH + kk * 32;
        LDSM4(a[0][0], a[0][1], a[0][2], a[0][3], abase);
        LDSM4(a[1][0], a[1][1], a[1][2], a[1][3], abase + 5376);
        const uint32_t bbase = sb + SM_W2 + kk * 32;
        LDSM4(bf[0][0], bf[0][1], bf[1][0], bf[1][1], bbase + boff4W);
        LDSM4(bf[2][0], bf[2][1], bf[3][0], bf[3][1], bbase + boff4W + 5376);
        LDSM2(bf[4][0], bf[4][1], bbase + boff2W);
#pragma unroll
        for (int mt = 0; mt < 2; mt++)
#pragma unroll
            for (int nt = 0; nt < 5; nt++) mma16(acc[mt][nt], a[mt], bf[nt]);
    }

    // ---- epilogue2: pair = relu(acc + b2) . W3; reduce; write out ----
#pragma unroll
    for (int mt = 0; mt < 2; mt++) {
        float s0 = 0.f, s1 = 0.f;
#pragma unroll
        for (int nt = 0; nt < 5; nt++) {
            const int col = wn * 40 + nt * 8 + 2 * tig;
            s0 += fmaxf(acc[mt][nt][0] + b2_s[col], 0.f) * w3_s[col];
            s0 += fmaxf(acc[mt][nt][1] + b2_s[col + 1], 0.f) * w3_s[col + 1];
            s1 += fmaxf(acc[mt][nt][2] + b2_s[col], 0.f) * w3_s[col];
            s1 += fmaxf(acc[mt][nt][3] + b2_s[col + 1], 0.f) * w3_s[col + 1];
        }
        s0 += __shfl_xor_sync(0xffffffffu, s0, 1);
        s0 += __shfl_xor_sync(0xffffffffu, s0, 2);
        s1 += __shfl_xor_sync(0xffffffffu, s1, 1);
        s1 += __shfl_xor_sync(0xffffffffu, s1, 2);
        if (tig == 0) {
            prb[wn * 64 + wm * 32 + mt * 16 + grp] = s0;
            prb[wn * 64 + wm * 32 + mt * 16 + grp + 8] = s1;
        }
    }
    __syncthreads();

    if (tid < 64) {
        const int j = j0 + tid;
        float pair = prb[tid] + prb[64 + tid] + prb[128 + tid] + prb[192 + tid] + b3[0];
        float mi = ment[b * NN + i];
        float mj = ment[b * NN + j];
        out[(size_t)(b * NN + i) * NN + j] = (mi + mj + pair) * (1.f / 3.f);
    }
}

// ---------------------------------------------------------------------------
extern "C" void kernel_launch(void* const* d_in, const int* in_sizes, int n_in,
                              void* d_out, int out_size) {
    const float* g  = (const float*)d_in[0];
    const float* m  = (const float*)d_in[1];
    const float* W1 = (const float*)d_in[2];
    const float* b1 = (const float*)d_in[3];
    const float* W2 = (const float*)d_in[4];
    const float* b2 = (const float*)d_in[5];
    const float* W3 = (const float*)d_in[6];
    const float* b3 = (const float*)d_in[7];
    float* out = (float*)d_out;
    (void)in_sizes; (void)n_in; (void)out_size;

    prep_kernel<<<544, 256>>>(g, W1, W2, b1);
    hihj_kernel<<<dim3(4, 16, 2), 256>>>(g, W1);
    cvt_hj_kernel<<<320, 256>>>();

    cudaFuncSetAttribute(pair_fp16, cudaFuncAttributeMaxDynamicSharedMemorySize, SMEM_BYTES);
    pair_fp16<<<dim3(NN / 64, NN, BB), 256, SMEM_BYTES>>>(m, b2, W3, b3, out);
}

// round 10
// speedup vs baseline: 2.0453x; 1.2665x over previous
#include <cuda_runtime.h>
#include <cuda_fp16.h>
#include <cstdint>

#define BB 2
#define NN 256
#define EE 512
#define HH 150
#define HP 160

// smem byte offsets (per 256-thread CTA, M=64)
#define STG_BYTES 17920  // A [64 x 80B] = 5120 + B [160 x 80B] = 12800
#define SM_STG 0         // 4 stages = 71680 (dead after GEMM1)
#define SM_W2  0         // phase2: W2T resident [160 x 336B] = 53760
#define SM_HF  53760     // h fwd: [64 x 336B] = 21504 (end 75264)
#define SM_HT  75264     // h transposed: 21504 (end 96768)
#define SM_GIH 96768     // g_i fp16 [512] = 1024
#define SM_HI  97792     // hi fp32 [160] (row i vector, incl b1)
#define SM_HJC 98432     // hj fp32 [160] (row i vector, for transposed)
#define SM_B2  99072     // b2 fp32 [160]
#define SM_W3  99712     // W3 fp32 [160]
#define SM_PRB 100352    // 4 x 64 fp32
#define SMEM_BYTES 101376

// device scratch
__device__ __half d_gh[BB * NN * EE];     // fp16 g
__device__ __half d_W1cTh[HP * EE];       // W1c^T [n][k] fp16, zero-padded
__device__ __half d_W2Th[HP * HP];        // W2^T  [n][k] fp16, zero-padded
__device__ float  d_hi[BB * NN * HP];     // g@W1a + b1 (fp32)
__device__ float  d_hj[BB * NN * HP];     // g@W1b (fp32 accum)
__device__ __half d_hjh[BB * NN * HP];    // fp16 copy of d_hj
__device__ __half d_hih[BB * NN * HP];    // fp16 copy of d_hi

// ---- helpers ----
__device__ __forceinline__ uint32_t h2mul(uint32_t a, uint32_t b) {
    uint32_t r;
    asm("mul.rn.f16x2 %0, %1, %2;" : "=r"(r) : "r"(a), "r"(b));
    return r;
}
__device__ __forceinline__ float2 h2f2(uint32_t h) {
    __half2 v = *reinterpret_cast<__half2*>(&h);
    return __half22float2(v);
}
__device__ __forceinline__ uint32_t f2h2(float lo, float hi) {
    uint32_t r;
    asm("cvt.rn.f16x2.f32 %0, %1, %2;" : "=r"(r) : "f"(hi), "f"(lo));
    return r;
}
__device__ __forceinline__ void cp16s(uint32_t dst, const void* src) {
    asm volatile("cp.async.cg.shared.global [%0], [%1], 16;" :: "r"(dst), "l"(src));
}
__device__ __forceinline__ void sts32(uint32_t a, uint32_t v) {
    asm volatile("st.shared.b32 [%0], %1;" :: "r"(a), "r"(v));
}
__device__ __forceinline__ uint32_t lds32(uint32_t a) {
    uint32_t v;
    asm volatile("ld.shared.b32 %0, [%1];" : "=r"(v) : "r"(a));
    return v;
}

#define LDSM4(r0, r1, r2, r3, a)                                              \
    asm volatile("ldmatrix.sync.aligned.m8n8.x4.shared.b16 {%0,%1,%2,%3}, [%4];" \
                 : "=r"(r0), "=r"(r1), "=r"(r2), "=r"(r3) : "r"(a))
#define LDSM2(r0, r1, a)                                                      \
    asm volatile("ldmatrix.sync.aligned.m8n8.x2.shared.b16 {%0,%1}, [%2];"    \
                 : "=r"(r0), "=r"(r1) : "r"(a))

__device__ __forceinline__ void mma16(float* d, const uint32_t* a, const uint32_t* b) {
    asm volatile(
        "mma.sync.aligned.m16n8k16.row.col.f32.f16.f16.f32 "
        "{%0,%1,%2,%3},{%4,%5,%6,%7},{%8,%9},{%0,%1,%2,%3};"
        : "+f"(d[0]), "+f"(d[1]), "+f"(d[2]), "+f"(d[3])
        : "r"(a[0]), "r"(a[1]), "r"(a[2]), "r"(a[3]), "r"(b[0]), "r"(b[1]));
}

// ---------------------------------------------------------------------------
// prep: fp16 conversions/transposes/padding + hi/hj accumulator init
// ---------------------------------------------------------------------------
__global__ void prep_kernel(const float* __restrict__ g, const float* __restrict__ W1,
                            const float* __restrict__ W2, const float* __restrict__ b1) {
    const int S0 = BB * NN * EE, S1 = HP * EE, S2 = HP * HP, S4 = BB * NN * HP;
    const int total = S0 + S1 + S2 + S4 + S4;
    for (int idx = blockIdx.x * blockDim.x + threadIdx.x; idx < total;
         idx += gridDim.x * blockDim.x) {
        int t = idx;
        if (t < S0) { d_gh[t] = __float2half(g[t]); continue; }
        t -= S0;
        if (t < S1) {
            int n = t >> 9, k = t & 511;
            d_W1cTh[t] = (n < HH) ? __float2half(W1[(size_t)(2 * EE + k) * HH + n])
                                  : __float2half(0.f);
            continue;
        }
        t -= S1;
        if (t < S2) {
            int n = t / HP, k = t % HP;
            d_W2Th[t] = (n < HH && k < HH) ? __float2half(W2[(size_t)k * HH + n])
                                           : __float2half(0.f);
            continue;
        }
        t -= S2;
        if (t < S4) { int c = t % HP; d_hi[t] = (c < HH) ? b1[c] : 0.f; continue; }
        t -= S4;
        d_hj[t] = 0.f;
    }
}

// ---------------------------------------------------------------------------
// hi/hj precompute: g@W1a (+b1 already in d_hi), g@W1b. K-split x4 + atomicAdd.
// ---------------------------------------------------------------------------
__global__ void hihj_kernel(const float* __restrict__ g, const float* __restrict__ W1) {
    __shared__ float gs[32][33];
    __shared__ float Ws[32][HP];
    const int tid = threadIdx.x;
    const int kz = blockIdx.x, rb = blockIdx.y, half = blockIdx.z;
    const int row0 = rb * 32;
    const int k0 = kz * 128;
    const int ty = tid >> 4, tx = tid & 15;

    float acc[2][10];
#pragma unroll
    for (int u = 0; u < 2; u++)
#pragma unroll
        for (int v = 0; v < 10; v++) acc[u][v] = 0.f;

    for (int kk = 0; kk < 4; kk++) {
        const int kbase = k0 + kk * 32;
        for (int q = tid; q < 32 * 32; q += 256) {
            int r = q >> 5, c = q & 31;
            gs[r][c] = g[(size_t)(row0 + r) * EE + kbase + c];
        }
        for (int q = tid; q < 32 * HP; q += 256) {
            int r = q / HP, c = q % HP;
            Ws[r][c] = (c < HH) ? W1[(size_t)(half * 512 + kbase + r) * HH + c] : 0.f;
        }
        __syncthreads();
#pragma unroll 4
        for (int k = 0; k < 32; k++) {
            float g0 = gs[ty * 2][k], g1 = gs[ty * 2 + 1][k];
#pragma unroll
            for (int v = 0; v < 10; v++) {
                float w = Ws[k][tx * 10 + v];
                acc[0][v] += g0 * w;
                acc[1][v] += g1 * w;
            }
        }
        __syncthreads();
    }
    float* dst = half ? d_hj : d_hi;
#pragma unroll
    for (int u = 0; u < 2; u++)
#pragma unroll
        for (int v = 0; v < 10; v++)
            atomicAdd(&dst[(size_t)(row0 + ty * 2 + u) * HP + tx * 10 + v], acc[u][v]);
}

__global__ void cvt_hj_kernel() {
    int t = blockIdx.x * 256 + threadIdx.x;
    if (t < BB * NN * HP) {
        d_hjh[t] = __float2half(d_hj[t]);
        d_hih[t] = __float2half(d_hi[t]);
    }
}

// ---------------------------------------------------------------------------
// main fused kernel, symmetric hij reuse. CTA = (tri-index, -, b).
// M=64 j-rows, 256 threads, 8 warps 2(M)x4(N), warp tile 32x40.
// Computes hij once; forward pass -> out[i, j0..j0+63]; if i < j0 also
// transposed pass -> out[j0..j0+63, i].
// ---------------------------------------------------------------------------
__global__ __launch_bounds__(256, 2) void pair_fp16(
    const float* __restrict__ ment, const float* __restrict__ b2,
    const float* __restrict__ W3, const float* __restrict__ b3,
    float* __restrict__ out) {
    extern __shared__ __align__(16) unsigned char smem[];
    const uint32_t sb = (uint32_t)__cvta_generic_to_shared(smem);
    float* hi_s  = (float*)(smem + SM_HI);
    float* hjc_s = (float*)(smem + SM_HJC);
    float* b2_s  = (float*)(smem + SM_B2);
    float* w3_s  = (float*)(smem + SM_W3);
    float* prb   = (float*)(smem + SM_PRB);

    const int tid = threadIdx.x, wid = tid >> 5, lane = tid & 31;
    const int b = blockIdx.z;
    // triangle decode: blockIdx.x in [0,640) -> (jb, i) with i <= jb*64+63
    int t = blockIdx.x, jb, i;
    if (t < 64)       { jb = 0; i = t; }
    else if (t < 192) { jb = 1; i = t - 64; }
    else if (t < 384) { jb = 2; i = t - 192; }
    else              { jb = 3; i = t - 384; }
    const int j0 = jb * 64;
    const bool has_t = (i < j0);
    const int wm = wid >> 2, wn = wid & 3, grp = lane >> 2, tig = lane & 3;

    for (int q = tid; q < HP; q += 256) {
        hi_s[q]  = d_hi[(size_t)(b * NN + i) * HP + q];
        hjc_s[q] = d_hj[(size_t)(b * NN + i) * HP + q];
        b2_s[q]  = (q < HH) ? b2[q] : 0.f;
        w3_s[q]  = (q < HH) ? W3[q] : 0.f;
    }

    const __half* gj = d_gh + (size_t)(b * NN + j0) * EE;
    const __half* gi = d_gh + (size_t)(b * NN + i) * EE;

    // ldmatrix lane-address offsets (conflict-free: strides 80B / 336B)
    const uint32_t arow = (uint32_t)(wm * 32 + (lane & 7) + ((lane >> 3) & 1) * 8);
    const uint32_t aoff  = arow * 80 + (lane >> 4) * 16;
    const uint32_t aoffH = arow * 336 + (lane >> 4) * 16;
    const uint32_t b4row = (uint32_t)(wn * 40 + (lane & 7) + ((lane >> 4) & 1) * 8);
    const uint32_t b2row = (uint32_t)(wn * 40 + 32 + (lane & 7));
    const uint32_t boff4  = b4row * 80 + ((lane >> 3) & 1) * 16;
    const uint32_t boff2  = b2row * 80 + ((lane >> 3) & 1) * 16;
    const uint32_t boff4W = b4row * 336 + ((lane >> 3) & 1) * 16;
    const uint32_t boff2W = b2row * 336 + ((lane >> 3) & 1) * 16;

    // ---- prologue: gi (fp16) + stages 0..2 ----
    if (tid < 64) cp16s(sb + SM_GIH + tid * 16, gi + tid * 8);
#pragma unroll
    for (int s = 0; s < 3; s++) {
        {
            int row = tid >> 2, u = tid & 3;
            cp16s(sb + SM_STG + s * STG_BYTES + row * 80 + u * 16,
                  gj + (size_t)row * EE + s * 32 + u * 8);
        }
#pragma unroll
        for (int tt = 0; tt < 3; tt++) {
            int q = tid + tt * 256;
            if (q < 640) {
                int n = q >> 2, u = q & 3;
                cp16s(sb + SM_STG + s * STG_BYTES + 5120 + n * 80 + u * 16,
                      d_W1cTh + (size_t)n * EE + s * 32 + u * 8);
            }
        }
        asm volatile("cp.async.commit_group;");
    }

    // ---- GEMM1: K=512 in 16 chunks of 32, 4-stage pipeline ----
    float acc[2][5][4];
#pragma unroll
    for (int x = 0; x < 2; x++)
#pragma unroll
        for (int y = 0; y < 5; y++)
#pragma unroll
            for (int e = 0; e < 4; e++) acc[x][y][e] = 0.f;

    for (int kc = 0; kc < 16; kc++) {
        asm volatile("cp.async.wait_group 2;");
        __syncthreads();
        if (kc < 13) {
            const int s = (kc + 3) & 3, kn = kc + 3;
            {
                int row = tid >> 2, u = tid & 3;
                cp16s(sb + SM_STG + s * STG_BYTES + row * 80 + u * 16,
                      gj + (size_t)row * EE + kn * 32 + u * 8);
            }
#pragma unroll
            for (int tt = 0; tt < 3; tt++) {
                int q = tid + tt * 256;
                if (q < 640) {
                    int n = q >> 2, u = q & 3;
                    cp16s(sb + SM_STG + s * STG_BYTES + 5120 + n * 80 + u * 16,
                          d_W1cTh + (size_t)n * EE + kn * 32 + u * 8);
                }
            }
        }
        asm volatile("cp.async.commit_group;");

        const uint32_t base = sb + SM_STG + (kc & 3) * STG_BYTES;
#pragma unroll
        for (int ks = 0; ks < 2; ks++) {
            const uint32_t g01 = lds32(sb + SM_GIH + kc * 64 + ks * 32 + tig * 4);
            const uint32_t g23 = lds32(sb + SM_GIH + kc * 64 + ks * 32 + tig * 4 + 16);
            uint32_t a[2][4], bf[5][2];
            const uint32_t abase = base + aoff + ks * 32;
            LDSM4(a[0][0], a[0][1], a[0][2], a[0][3], abase);
            LDSM4(a[1][0], a[1][1], a[1][2], a[1][3], abase + 1280);
#pragma unroll
            for (int mt = 0; mt < 2; mt++) {
                a[mt][0] = h2mul(a[mt][0], g01);
                a[mt][1] = h2mul(a[mt][1], g01);
                a[mt][2] = h2mul(a[mt][2], g23);
                a[mt][3] = h2mul(a[mt][3], g23);
            }
            const uint32_t bbase = base + 5120 + ks * 32;
            LDSM4(bf[0][0], bf[0][1], bf[1][0], bf[1][1], bbase + boff4);
            LDSM4(bf[2][0], bf[2][1], bf[3][0], bf[3][1], bbase + boff4 + 1280);
            LDSM2(bf[4][0], bf[4][1], bbase + boff2);
#pragma unroll
            for (int mt = 0; mt < 2; mt++)
#pragma unroll
                for (int nt = 0; nt < 5; nt++) mma16(acc[mt][nt], a[mt], bf[nt]);
        }
    }
    __syncthreads();   // stage reads done before W2 overwrites region

    // ---- prefetch full W2T into SM_W2 (overlaps epilogue1) ----
#pragma unroll
    for (int tt = 0; tt < 13; tt++) {
        int q = tid + tt * 256;
        if (q < 3200) {
            int n = q / 20, u = q % 20;
            cp16s(sb + SM_W2 + n * 336 + u * 16, d_W2Th + (size_t)n * HP + u * 8);
        }
    }
    asm volatile("cp.async.commit_group;");

    // ---- epilogue1: build h_fwd (and h_t if has_t) from acc ----
#pragma unroll
    for (int mt = 0; mt < 2; mt++) {
#pragma unroll
        for (int hrow = 0; hrow < 2; hrow++) {
            const int r = wm * 32 + mt * 16 + grp + hrow * 8;
            const __half* hjrow = d_hjh + (size_t)(b * NN + j0 + r) * HP;
            const __half* hirow = d_hih + (size_t)(b * NN + j0 + r) * HP;
#pragma unroll
            for (int nt = 0; nt < 5; nt++) {
                const int col = wn * 40 + nt * 8 + 2 * tig;
                const float a0 = acc[mt][nt][hrow * 2 + 0];
                const float a1 = acc[mt][nt][hrow * 2 + 1];
                // forward: hi[i] const + hj[j] row
                float2 hjf = h2f2(*(const uint32_t*)(hjrow + col));
                float x0 = fmaxf(a0 + hi_s[col] + hjf.x, 0.f);
                float x1 = fmaxf(a1 + hi_s[col + 1] + hjf.y, 0.f);
                sts32(sb + SM_HF + r * 336 + col * 2, f2h2(x0, x1));
                if (has_t) {
                    // transposed: hi[j] row + hj[i] const
                    float2 hif = h2f2(*(const uint32_t*)(hirow + col));
                    float y0 = fmaxf(a0 + hif.x + hjc_s[col], 0.f);
                    float y1 = fmaxf(a1 + hif.y + hjc_s[col + 1], 0.f);
                    sts32(sb + SM_HT + r * 336 + col * 2, f2h2(y0, y1));
                }
            }
        }
    }
    asm volatile("cp.async.wait_group 0;");
    __syncthreads();

    // ---- two GEMM2+epilogue2 passes (fwd always, transposed if has_t) ----
#pragma unroll 1
    for (int pass = 0; pass < 2; pass++) {
        if (pass == 1 && !has_t) break;
        const uint32_t hbase = sb + (pass ? SM_HT : SM_HF) + aoffH;

#pragma unroll
        for (int x = 0; x < 2; x++)
#pragma unroll
            for (int y = 0; y < 5; y++)
#pragma unroll
                for (int e = 0; e < 4; e++) acc[x][y][e] = 0.f;

#pragma unroll
        for (int kk = 0; kk < 10; kk++) {
            uint32_t a[2][4], bf[5][2];
            const uint32_t abase = hbase + kk * 32;
            LDSM4(a[0][0], a[0][1], a[0][2], a[0][3], abase);
            LDSM4(a[1][0], a[1][1], a[1][2], a[1][3], abase + 5376);
            const uint32_t bbase = sb + SM_W2 + kk * 32;
            LDSM4(bf[0][0], bf[0][1], bf[1][0], bf[1][1], bbase + boff4W);
            LDSM4(bf[2][0], bf[2][1], bf[3][0], bf[3][1], bbase + boff4W + 5376);
            LDSM2(bf[4][0], bf[4][1], bbase + boff2W);
#pragma unroll
            for (int mt = 0; mt < 2; mt++)
#pragma unroll
                for (int nt = 0; nt < 5; nt++) mma16(acc[mt][nt], a[mt], bf[nt]);
        }

#pragma unroll
        for (int mt = 0; mt < 2; mt++) {
            float s0 = 0.f, s1 = 0.f;
#pragma unroll
            for (int nt = 0; nt < 5; nt++) {
                const int col = wn * 40 + nt * 8 + 2 * tig;
                s0 += fmaxf(acc[mt][nt][0] + b2_s[col], 0.f) * w3_s[col];
                s0 += fmaxf(acc[mt][nt][1] + b2_s[col + 1], 0.f) * w3_s[col + 1];
                s1 += fmaxf(acc[mt][nt][2] + b2_s[col], 0.f) * w3_s[col];
                s1 += fmaxf(acc[mt][nt][3] + b2_s[col + 1], 0.f) * w3_s[col + 1];
            }
            s0 += __shfl_xor_sync(0xffffffffu, s0, 1);
            s0 += __shfl_xor_sync(0xffffffffu, s0, 2);
            s1 += __shfl_xor_sync(0xffffffffu, s1, 1);
            s1 += __shfl_xor_sync(0xffffffffu, s1, 2);
            if (tig == 0) {
                prb[wn * 64 + wm * 32 + mt * 16 + grp] = s0;
                prb[wn * 64 + wm * 32 + mt * 16 + grp + 8] = s1;
            }
        }
        __syncthreads();

        if (tid < 64) {
            const int j = j0 + tid;
            float pair = prb[tid] + prb[64 + tid] + prb[128 + tid] + prb[192 + tid] + b3[0];
            float mi = ment[b * NN + i];
            float mj = ment[b * NN + j];
            float val = (mi + mj + pair) * (1.f / 3.f);
            if (pass == 0)
                out[(size_t)(b * NN + i) * NN + j] = val;
            else
                out[(size_t)(b * NN + j) * NN + i] = val;
        }
        __syncthreads();   // prb reads done before next pass overwrites
    }
}

// ---------------------------------------------------------------------------
extern "C" void kernel_launch(void* const* d_in, const int* in_sizes, int n_in,
                              void* d_out, int out_size) {
    const float* g  = (const float*)d_in[0];
    const float* m  = (const float*)d_in[1];
    const float* W1 = (const float*)d_in[2];
    const float* b1 = (const float*)d_in[3];
    const float* W2 = (const float*)d_in[4];
    const float* b2 = (const float*)d_in[5];
    const float* W3 = (const float*)d_in[6];
    const float* b3 = (const float*)d_in[7];
    float* out = (float*)d_out;
    (void)in_sizes; (void)n_in; (void)out_size;

    prep_kernel<<<544, 256>>>(g, W1, W2, b1);
    hihj_kernel<<<dim3(4, 16, 2), 256>>>(g, W1);
    cvt_hj_kernel<<<320, 256>>>();

    cudaFuncSetAttribute(pair_fp16, cudaFuncAttributeMaxDynamicSharedMemorySize, SMEM_BYTES);
    pair_fp16<<<dim3(640, 1, BB), 256, SMEM_BYTES>>>(m, b2, W3, b3, out);
}